// round 1
// baseline (speedup 1.0000x reference)
#include <cuda_runtime.h>
#include <math.h>

// ---------------------------------------------------------------------------
// MVAEdecoder: blended-expert MLP.
//   g  = concat(x,z)                     [4096, 864]
//   h1 = elu(g @ Wg1^T + bg1)            [4096, 128]
//   h2 = elu(h1 @ Wg2^T + bg2)           [4096, 128]
//   bc = softmax(h2 @ Wg3^T + bg3)       [4096, 8]
//   h  = elu(blend(bc, concat(x,z), W0, b0))   [4096, 1024]
//   h  = elu(blend(bc, concat(h,z), W1, b1))
//   h  = elu(blend(bc, concat(h,z), W2, b2))
//   out =     blend(bc, h,           W3, b3)   [4096, 768]
//
// blend(bc, inp, W, b)[b,o] = sum_e bc[b,e] * (W[e,o,:]·inp[b,:] + b[e,o])
//                           = GEMM with K' = E*IN, A'[b, e*IN+k] = bc[b,e]*inp[b,k]
// The bc scaling is applied during the A smem load (each K-tile of width 16
// lies inside a single expert since IN % 16 == 0 for every layer).
// ---------------------------------------------------------------------------

#define MB 4096
#define XD 800
#define ZD 64
#define HD 1024
#define OD 768
#define GHD 128
#define NE 8

// scratch (static __device__ arrays: allocation-free per harness rules)
__device__ __align__(16) float g_G [MB * (XD + ZD)];   // concat(x,z)  [4096,864]
__device__ __align__(16) float g_H1[MB * GHD];
__device__ __align__(16) float g_H2[MB * GHD];
__device__ __align__(16) float g_BC[MB * NE];
__device__ __align__(16) float g_HA[MB * (HD + ZD)];   // [4096,1088] (z in cols 1024..1087)
__device__ __align__(16) float g_HB[MB * (HD + ZD)];

// ---------------------------------------------------------------------------
// prep: build G = concat(x,z) and pre-fill the z columns of HA / HB
// ---------------------------------------------------------------------------
__global__ void prep_kernel(const float* __restrict__ x, const float* __restrict__ z,
                            float* __restrict__ G, float* __restrict__ HA,
                            float* __restrict__ HB) {
    int i = blockIdx.x * blockDim.x + threadIdx.x;
    const int totG = MB * (XD + ZD);
    if (i < totG) {
        int b = i / (XD + ZD), c = i - b * (XD + ZD);
        G[i] = (c < XD) ? x[b * XD + c] : z[b * ZD + (c - XD)];
    }
    const int totZ = MB * ZD;
    if (i < totZ) {
        int b = i / ZD, c = i - b * ZD;
        float v = z[i];
        HA[b * (HD + ZD) + HD + c] = v;
        HB[b * (HD + ZD) + HD + c] = v;
    }
}

// ---------------------------------------------------------------------------
// Tiled fp32 GEMM with optional per-(row,expert) A-scaling + blended bias + ELU.
//   C[m, n] = act( sum_{e,k} (bc[m,e]*A[m,k]) * W[e, n, k]  +  sum_e bc[m,e]*bias[e,n] )
// HAS_BC=false => E=1, no scaling, bias = bias[n].
// BM=BN=128, BK=16, 256 threads, 8x8 per thread. Requires M%128==0, Nout%128==0,
// IN%16==0, lda%4==0.
// ---------------------------------------------------------------------------
#define BMT 128
#define BNT 128
#define BKT 16

template <bool HAS_BC>
__global__ __launch_bounds__(256, 2)
void moe_gemm_kernel(const float* __restrict__ A, int lda, int IN,
                     const float* __restrict__ W,      // [E, Nout, IN]
                     const float* __restrict__ bias,   // [E, Nout]
                     const float* __restrict__ bc,     // [M, 8] (HAS_BC only)
                     int Nout,
                     float* __restrict__ C, int ldc, int applyElu) {
    __shared__ float As[BKT][BMT];
    __shared__ float Bs[BKT][BNT];

    const int tid = threadIdx.x;            // 0..255
    const int tx = tid & 15;                 // 0..15
    const int ty = tid >> 4;                 // 0..15
    const int mBase = blockIdx.y * BMT;
    const int nBase = blockIdx.x * BNT;

    const int E = HAS_BC ? NE : 1;
    const int Ktot = E * IN;

    // loader lane mapping (512 float4 per tile per operand; 2 per thread)
    const int aRow = tid >> 2;               // 0..63
    const int aVec = (tid & 3) << 2;          // 0,4,8,12

    float acc[8][8];
#pragma unroll
    for (int i = 0; i < 8; i++)
#pragma unroll
        for (int j = 0; j < 8; j++) acc[i][j] = 0.f;

    int e = 0, kin = 0;
    for (int k0 = 0; k0 < Ktot; k0 += BKT) {
        // ---- load A tile (scaled by bc) ----
#pragma unroll
        for (int rr = 0; rr < 2; rr++) {
            int r = aRow + rr * 64;
            int grow = mBase + r;
            float4 v = *reinterpret_cast<const float4*>(A + (size_t)grow * lda + kin + aVec);
            float s = 1.f;
            if (HAS_BC) s = __ldg(bc + grow * NE + e);
            As[aVec + 0][r] = v.x * s;
            As[aVec + 1][r] = v.y * s;
            As[aVec + 2][r] = v.z * s;
            As[aVec + 3][r] = v.w * s;
        }
        // ---- load W tile ----
#pragma unroll
        for (int rr = 0; rr < 2; rr++) {
            int o = aRow + rr * 64;
            int go = nBase + o;
            float4 v = *reinterpret_cast<const float4*>(
                W + ((size_t)e * Nout + go) * IN + kin + aVec);
            Bs[aVec + 0][o] = v.x;
            Bs[aVec + 1][o] = v.y;
            Bs[aVec + 2][o] = v.z;
            Bs[aVec + 3][o] = v.w;
        }
        __syncthreads();

#pragma unroll
        for (int k = 0; k < BKT; k++) {
            float4 a0 = *reinterpret_cast<const float4*>(&As[k][ty * 8]);
            float4 a1 = *reinterpret_cast<const float4*>(&As[k][ty * 8 + 4]);
            float4 b0 = *reinterpret_cast<const float4*>(&Bs[k][tx * 8]);
            float4 b1 = *reinterpret_cast<const float4*>(&Bs[k][tx * 8 + 4]);
            float av[8] = {a0.x, a0.y, a0.z, a0.w, a1.x, a1.y, a1.z, a1.w};
            float bv[8] = {b0.x, b0.y, b0.z, b0.w, b1.x, b1.y, b1.z, b1.w};
#pragma unroll
            for (int i = 0; i < 8; i++)
#pragma unroll
                for (int j = 0; j < 8; j++) acc[i][j] = fmaf(av[i], bv[j], acc[i][j]);
        }
        __syncthreads();

        kin += BKT;
        if (kin == IN) { kin = 0; e++; }
    }

    // ---- epilogue: blended bias + optional ELU ----
#pragma unroll
    for (int i = 0; i < 8; i++) {
        int grow = mBase + ty * 8 + i;
        float bcv[NE];
        if (HAS_BC) {
#pragma unroll
            for (int ee = 0; ee < NE; ee++) bcv[ee] = __ldg(bc + grow * NE + ee);
        }
#pragma unroll
        for (int j = 0; j < 8; j++) {
            int gcol = nBase + tx * 8 + j;
            float bb;
            if (HAS_BC) {
                bb = 0.f;
#pragma unroll
                for (int ee = 0; ee < NE; ee++)
                    bb = fmaf(bcv[ee], __ldg(bias + ee * Nout + gcol), bb);
            } else {
                bb = __ldg(bias + gcol);
            }
            float v = acc[i][j] + bb;
            if (applyElu) v = (v > 0.f) ? v : expm1f(v);
            C[(size_t)grow * ldc + gcol] = v;
        }
    }
}

// ---------------------------------------------------------------------------
// gate3 + softmax: bc[b,e] = softmax_e( h2[b,:]·Wg3[e,:] + bg3[e] )
// one warp per row
// ---------------------------------------------------------------------------
__global__ void gate3_softmax_kernel(const float* __restrict__ H2,
                                     const float* __restrict__ Wg3,
                                     const float* __restrict__ bg3,
                                     float* __restrict__ BC) {
    int warp = (blockIdx.x * blockDim.x + threadIdx.x) >> 5;
    int lane = threadIdx.x & 31;
    if (warp >= MB) return;

    const float* h = H2 + (size_t)warp * GHD;
    float hv[4];
#pragma unroll
    for (int t = 0; t < 4; t++) hv[t] = h[lane + 32 * t];

    float s[NE];
#pragma unroll
    for (int eidx = 0; eidx < NE; eidx++) {
        float p = 0.f;
#pragma unroll
        for (int t = 0; t < 4; t++)
            p = fmaf(hv[t], __ldg(Wg3 + eidx * GHD + lane + 32 * t), p);
#pragma unroll
        for (int off = 16; off > 0; off >>= 1) p += __shfl_xor_sync(0xFFFFFFFFu, p, off);
        s[eidx] = p + __ldg(bg3 + eidx);
    }
    float mx = s[0];
#pragma unroll
    for (int eidx = 1; eidx < NE; eidx++) mx = fmaxf(mx, s[eidx]);
    float sum = 0.f;
#pragma unroll
    for (int eidx = 0; eidx < NE; eidx++) { s[eidx] = expf(s[eidx] - mx); sum += s[eidx]; }
    float inv = 1.f / sum;
    if (lane < NE) BC[(size_t)warp * NE + lane] = s[lane] * inv;
}

// ---------------------------------------------------------------------------
extern "C" void kernel_launch(void* const* d_in, const int* in_sizes, int n_in,
                              void* d_out, int out_size) {
    const float* x   = (const float*)d_in[0];
    const float* z   = (const float*)d_in[1];
    const float* Wg1 = (const float*)d_in[2];
    const float* bg1 = (const float*)d_in[3];
    const float* Wg2 = (const float*)d_in[4];
    const float* bg2 = (const float*)d_in[5];
    const float* Wg3 = (const float*)d_in[6];
    const float* bg3 = (const float*)d_in[7];
    const float* W0  = (const float*)d_in[8];
    const float* b0  = (const float*)d_in[9];
    const float* W1  = (const float*)d_in[10];
    const float* b1  = (const float*)d_in[11];
    const float* W2  = (const float*)d_in[12];
    const float* b2  = (const float*)d_in[13];
    const float* W3  = (const float*)d_in[14];
    const float* b3  = (const float*)d_in[15];
    float* out = (float*)d_out;

    float *G, *H1, *H2, *BC, *HA, *HB;
    cudaGetSymbolAddress((void**)&G,  g_G);
    cudaGetSymbolAddress((void**)&H1, g_H1);
    cudaGetSymbolAddress((void**)&H2, g_H2);
    cudaGetSymbolAddress((void**)&BC, g_BC);
    cudaGetSymbolAddress((void**)&HA, g_HA);
    cudaGetSymbolAddress((void**)&HB, g_HB);

    const int GW = XD + ZD;   // 864
    const int HW = HD + ZD;   // 1088

    // prep: concat + z-column fill
    {
        int tot = MB * GW;
        prep_kernel<<<(tot + 255) / 256, 256>>>(x, z, G, HA, HB);
    }

    // gate layer 1: [4096,864] @ Wg1^T -> [4096,128], elu
    moe_gemm_kernel<false><<<dim3(GHD / BNT, MB / BMT), 256>>>(
        G, GW, GW, Wg1, bg1, nullptr, GHD, H1, GHD, 1);
    // gate layer 2: [4096,128] @ Wg2^T -> [4096,128], elu
    moe_gemm_kernel<false><<<dim3(GHD / BNT, MB / BMT), 256>>>(
        H1, GHD, GHD, Wg2, bg2, nullptr, GHD, H2, GHD, 1);
    // gate layer 3 + softmax -> BC [4096,8]
    gate3_softmax_kernel<<<(MB * 32 + 255) / 256, 256>>>(H2, Wg3, bg3, BC);

    // expert layer 0: inp = G [4096,864], K' = 8*864 = 6912 -> HA[:, :1024], elu
    moe_gemm_kernel<true><<<dim3(HD / BNT, MB / BMT), 256>>>(
        G, GW, GW, W0, b0, BC, HD, HA, HW, 1);
    // expert layer 1: inp = HA [4096,1088], K' = 8*1088 -> HB[:, :1024], elu
    moe_gemm_kernel<true><<<dim3(HD / BNT, MB / BMT), 256>>>(
        HA, HW, HW, W1, b1, BC, HD, HB, HW, 1);
    // expert layer 2: inp = HB -> HA[:, :1024], elu
    moe_gemm_kernel<true><<<dim3(HD / BNT, MB / BMT), 256>>>(
        HB, HW, HW, W2, b2, BC, HD, HA, HW, 1);
    // expert layer 3: inp = HA cols 0..1023 (IN=1024, lda=1088) -> out [4096,768], no act
    moe_gemm_kernel<true><<<dim3(OD / BNT, MB / BMT), 256>>>(
        HA, HW, HD, W3, b3, BC, OD, out, OD, 0);
}